// round 1
// baseline (speedup 1.0000x reference)
#include <cuda_runtime.h>
#include <cuda_bf16.h>

// Q_Model_43782896615432 — analytic collapse of the 6-qubit circuit.
//
// Math: after RX(theta_w) on |0>, each qubit is product Bernoulli with
// E[(-1)^x] = cos(theta). CNOTs are basis permutations; tracking XORs through
// the CNOT chain (0,1),(1,2),(2,0),(3,4),(4,5),(5,3):
//   Z0 = c1*c2, Z1 = c0*c1, Z2 = c0*c1*c2,
//   Z3 = c4*c5, Z4 = c3*c4, Z5 = c3*c4*c5,  c_w = cos(theta_w)
// theta[0:3] = sen @ W_sen^T + b_sen, theta[3:6] = sa @ W_sar^T + b_sar.
// sar = Z[3:6] @ W_resar^T + b_resar ; sen_out = Z[0:3] @ W_resen^T + b_resen.

#define BQ 262144
#define NGROUPS (BQ / 4)   // 4 samples per thread -> all float4-aligned I/O

__global__ __launch_bounds__(256)
void q_model_kernel(const float* __restrict__ sa,
                    const float* __restrict__ sen,
                    const float* __restrict__ W_sar,  const float* __restrict__ b_sar,
                    const float* __restrict__ W_sen,  const float* __restrict__ b_sen,
                    const float* __restrict__ W_resar, const float* __restrict__ b_resar,
                    const float* __restrict__ W_resen, const float* __restrict__ b_resen,
                    float* __restrict__ out)
{
    const int g = blockIdx.x * blockDim.x + threadIdx.x;
    if (g >= NGROUPS) return;

    // ---- uniform weight loads (hit L1/uniform path; hoisted by ptxas) ----
    float wsar[9], wsen[9], wre[9], wra[6];
    float bsar[3], bsen[3], bre[3], bra[2];
#pragma unroll
    for (int i = 0; i < 9; i++) {
        wsar[i] = __ldg(W_sar + i);
        wsen[i] = __ldg(W_sen + i);
        wre[i]  = __ldg(W_resen + i);
    }
#pragma unroll
    for (int i = 0; i < 6; i++) wra[i] = __ldg(W_resar + i);
#pragma unroll
    for (int i = 0; i < 3; i++) {
        bsar[i] = __ldg(b_sar + i);
        bsen[i] = __ldg(b_sen + i);
        bre[i]  = __ldg(b_resen + i);
    }
    bra[0] = __ldg(b_resar + 0);
    bra[1] = __ldg(b_resar + 1);

    // ---- vectorized input: 12 floats = 4 samples of 3 ----
    const float4* sa4  = reinterpret_cast<const float4*>(sa);
    const float4* sen4 = reinterpret_cast<const float4*>(sen);
    float4 A0 = sa4[3 * g + 0], A1 = sa4[3 * g + 1], A2 = sa4[3 * g + 2];
    float4 E0 = sen4[3 * g + 0], E1 = sen4[3 * g + 1], E2 = sen4[3 * g + 2];

    float a[12] = {A0.x, A0.y, A0.z, A0.w, A1.x, A1.y, A1.z, A1.w, A2.x, A2.y, A2.z, A2.w};
    float e[12] = {E0.x, E0.y, E0.z, E0.w, E1.x, E1.y, E1.z, E1.w, E2.x, E2.y, E2.z, E2.w};

    float sarv[8];   // 4 samples x 2
    float senv[12];  // 4 samples x 3

#pragma unroll
    for (int s = 0; s < 4; s++) {
        const float a0 = a[3 * s + 0], a1 = a[3 * s + 1], a2 = a[3 * s + 2];
        const float e0 = e[3 * s + 0], e1 = e[3 * s + 1], e2 = e[3 * s + 2];

        // theta 0..2 from sen branch (wires 0-2), theta 3..5 from sa branch
        float t0 = fmaf(wsen[0], e0, fmaf(wsen[1], e1, fmaf(wsen[2], e2, bsen[0])));
        float t1 = fmaf(wsen[3], e0, fmaf(wsen[4], e1, fmaf(wsen[5], e2, bsen[1])));
        float t2 = fmaf(wsen[6], e0, fmaf(wsen[7], e1, fmaf(wsen[8], e2, bsen[2])));
        float t3 = fmaf(wsar[0], a0, fmaf(wsar[1], a1, fmaf(wsar[2], a2, bsar[0])));
        float t4 = fmaf(wsar[3], a0, fmaf(wsar[4], a1, fmaf(wsar[5], a2, bsar[1])));
        float t5 = fmaf(wsar[6], a0, fmaf(wsar[7], a1, fmaf(wsar[8], a2, bsar[2])));

        float c0 = __cosf(t0), c1 = __cosf(t1), c2 = __cosf(t2);
        float c3 = __cosf(t3), c4 = __cosf(t4), c5 = __cosf(t5);

        float Z0 = c1 * c2;
        float Z1 = c0 * c1;
        float Z2 = Z1 * c2;
        float Z3 = c4 * c5;
        float Z4 = c3 * c4;
        float Z5 = Z4 * c5;

        sarv[2 * s + 0] = fmaf(wra[0], Z3, fmaf(wra[1], Z4, fmaf(wra[2], Z5, bra[0])));
        sarv[2 * s + 1] = fmaf(wra[3], Z3, fmaf(wra[4], Z4, fmaf(wra[5], Z5, bra[1])));

        senv[3 * s + 0] = fmaf(wre[0], Z0, fmaf(wre[1], Z1, fmaf(wre[2], Z2, bre[0])));
        senv[3 * s + 1] = fmaf(wre[3], Z0, fmaf(wre[4], Z1, fmaf(wre[5], Z2, bre[1])));
        senv[3 * s + 2] = fmaf(wre[6], Z0, fmaf(wre[7], Z1, fmaf(wre[8], Z2, bre[2])));
    }

    // ---- vectorized output: sar block [0, 2B), sen block [2B, 5B) ----
    float4* osar = reinterpret_cast<float4*>(out);                 // 8 floats per group
    float4* osen = reinterpret_cast<float4*>(out + 2 * BQ);        // 12 floats per group
    osar[2 * g + 0] = make_float4(sarv[0], sarv[1], sarv[2], sarv[3]);
    osar[2 * g + 1] = make_float4(sarv[4], sarv[5], sarv[6], sarv[7]);
    osen[3 * g + 0] = make_float4(senv[0], senv[1], senv[2], senv[3]);
    osen[3 * g + 1] = make_float4(senv[4], senv[5], senv[6], senv[7]);
    osen[3 * g + 2] = make_float4(senv[8], senv[9], senv[10], senv[11]);
}

extern "C" void kernel_launch(void* const* d_in, const int* in_sizes, int n_in,
                              void* d_out, int out_size) {
    const float* sa      = (const float*)d_in[0];
    const float* sen     = (const float*)d_in[1];
    const float* W_sar   = (const float*)d_in[2];
    const float* b_sar   = (const float*)d_in[3];
    const float* W_sen   = (const float*)d_in[4];
    const float* b_sen   = (const float*)d_in[5];
    const float* W_resar = (const float*)d_in[6];
    const float* b_resar = (const float*)d_in[7];
    const float* W_resen = (const float*)d_in[8];
    const float* b_resen = (const float*)d_in[9];
    float* out = (float*)d_out;

    const int threads = 256;
    const int blocks  = (NGROUPS + threads - 1) / threads;  // 256
    q_model_kernel<<<blocks, threads>>>(sa, sen, W_sar, b_sar, W_sen, b_sen,
                                        W_resar, b_resar, W_resen, b_resen, out);
}